// round 3
// baseline (speedup 1.0000x reference)
#include <cuda_runtime.h>
#include <cuda_bf16.h>

// ---------------- problem constants ----------------
#define NB 16
#define NC 32
#define NH 192
#define NW 192
#define NE 8
#define HWSZ (NH*NW)

// conv tile: 8 rows x 64 cols per block, 32 outs
#define TH 8
#define TW 64
#define THREADS 256
#define GPITCH 68                 // 66 cols padded to 68 (even -> 16B-aligned rows)
#define GPLANE (10*GPITCH)        // 680 floats per g-plane
#define NPL 6                     // planes per chunk: 2 x-channels x 3 bases
#define NCHUNKS 16
#define WCH_ULL (NPL*9*32)        // 1728 duplicated weights per chunk
#define SMEM_BYTES (2*WCH_ULL*8 + 2*NPL*GPLANE*4)   // 27648 + 32640 = 60288

typedef unsigned long long ull;

// ---------------- device globals (scratch) ----------------
__device__ float g_gate[NB*NC];
__device__ float g_scale[NB];
__device__ float g_bias[NC*9];   // [o]: S,R0,R2,C0,C2,T00,T02,T20,T22
__device__ __align__(16) ull g_wdup[NCHUNKS*WCH_ULL];

// ---------------- helpers ----------------
__device__ __forceinline__ ull pack2(float lo, float hi) {
    ull r; asm("mov.b64 %0, {%1, %2};" : "=l"(r) : "f"(lo), "f"(hi)); return r;
}
__device__ __forceinline__ void unpack2(ull v, float& lo, float& hi) {
    asm("mov.b64 {%0, %1}, %2;" : "=f"(lo), "=f"(hi) : "l"(v));
}
__device__ __forceinline__ void fma2(ull& d, ull a, ull b) {
    asm("fma.rn.f32x2 %0, %1, %2, %3;" : "=l"(d) : "l"(a), "l"(b), "l"(d));
}
__device__ __forceinline__ float silu_f(float z) {
    float e = __expf(-z);
    return __fdividef(z, 1.0f + e);
}
__device__ __forceinline__ float fast_tanh(float x) {
    float e = __expf(2.0f * x);
    return 1.0f - __fdividef(2.0f, e + 1.0f);
}

// ---------------- kernel 1: gate_x = mean(x, H, W) ----------------
__global__ void k_gate_mean(const float* __restrict__ x) {
    int plane = blockIdx.x;
    const float* p = x + (size_t)plane * HWSZ;
    float s = 0.f;
    for (int i = threadIdx.x; i < HWSZ; i += 256) s += p[i];
    __shared__ float red[256];
    red[threadIdx.x] = s;
    __syncthreads();
    for (int off = 128; off > 0; off >>= 1) {
        if (threadIdx.x < off) red[threadIdx.x] += red[threadIdx.x + off];
        __syncthreads();
    }
    if (threadIdx.x == 0) g_gate[plane] = red[0] * (1.0f / (float)HWSZ);
}

// ---------------- kernel 2: gating ----------------
__device__ __forceinline__ float cv2_8(const float* v) {
    float m = 0.f;
    for (int i = 0; i < 8; ++i) m += v[i];
    m *= 0.125f;
    float var = 0.f;
    for (int i = 0; i < 8; ++i) { float d = v[i] - m; var += d * d; }
    var *= (1.0f / 7.0f);
    return var / (m * m + 1e-10f);
}

__global__ void k_gating(const float* __restrict__ wg, float* __restrict__ loss_out) {
    __shared__ float sgates[NB][NE];
    int n = threadIdx.x;
    if (n < NB) {
        float logit[NE];
        #pragma unroll
        for (int e = 0; e < NE; ++e) logit[e] = 0.f;
        for (int c = 0; c < NC; ++c) {
            float gx = g_gate[n * NC + c];
            #pragma unroll
            for (int e = 0; e < NE; ++e) logit[e] += gx * wg[c * NE + e];
        }
        float mx = logit[0];
        #pragma unroll
        for (int e = 1; e < NE; ++e) mx = fmaxf(mx, logit[e]);
        float pr[NE]; float se = 0.f;
        #pragma unroll
        for (int e = 0; e < NE; ++e) { pr[e] = __expf(logit[e] - mx); se += pr[e]; }
        float inv = 1.0f / se;
        #pragma unroll
        for (int e = 0; e < NE; ++e) pr[e] *= inv;
        int i0 = 0;
        #pragma unroll
        for (int e = 1; e < NE; ++e) if (pr[e] > pr[i0]) i0 = e;
        int i1 = (i0 == 0) ? 1 : 0;
        #pragma unroll
        for (int e = 0; e < NE; ++e) if (e != i0 && pr[e] > pr[i1]) i1 = e;
        float v0 = pr[i0], v1 = pr[i1];
        float denom = v0 + v1 + 1e-6f;
        #pragma unroll
        for (int e = 0; e < NE; ++e) sgates[n][e] = 0.f;
        sgates[n][i0] = v0 / denom;
        sgates[n][i1] = v1 / denom;
        g_scale[n] = (v0 + v1) / denom;
    }
    __syncthreads();
    if (threadIdx.x == 0) {
        float imp[NE], ld[NE];
        #pragma unroll
        for (int e = 0; e < NE; ++e) { imp[e] = 0.f; ld[e] = 0.f; }
        for (int b = 0; b < NB; ++b)
            for (int e = 0; e < NE; ++e) {
                float v = sgates[b][e];
                imp[e] += v;
                if (v > 0.f) ld[e] += 1.f;
            }
        *loss_out = 0.01f * (cv2_8(imp) + cv2_8(ld));
    }
}

// ---------------- kernel 3a: duplicated weight layout (bases 1..3) --------
// layout [cb][plane][tap][o], plane = c2*3 + bi, gi = (bi+1)*32 + cb*2 + c2
__global__ void k_wdup(const float* __restrict__ pw) {
    int idx = blockIdx.x * 256 + threadIdx.x;       // < 27648
    int o  = idx & 31;
    int k  = (idx >> 5) % 9;
    int t  = (idx >> 5) / 9;                        // 0..95 == cb*6 + plane
    int plane = t % 6;
    int cb = t / 6;
    int c2 = plane / 3;
    int bi = plane % 3;
    int gi = (bi + 1) * 32 + cb * 2 + c2;
    float w = pw[(size_t)o * (128 * 9) + gi * 9 + k];
    g_wdup[idx] = pack2(w, w);
}

// ---------------- kernel 3b: P0 bias tables ----------------
__global__ void k_bias(const float* __restrict__ pw) {
    int o = threadIdx.x;
    if (o >= 32) return;
    const float G0 = 0.7310585786300049f;   // silu(1)
    float T[9];
    #pragma unroll
    for (int k = 0; k < 9; ++k) T[k] = 0.f;
    for (int c = 0; c < 32; ++c)
        #pragma unroll
        for (int k = 0; k < 9; ++k) T[k] += pw[(size_t)o * (128 * 9) + c * 9 + k];
    #pragma unroll
    for (int k = 0; k < 9; ++k) T[k] *= G0;
    float S = 0.f;
    #pragma unroll
    for (int k = 0; k < 9; ++k) S += T[k];
    g_bias[o * 9 + 0] = S;
    g_bias[o * 9 + 1] = T[0] + T[1] + T[2];
    g_bias[o * 9 + 2] = T[6] + T[7] + T[8];
    g_bias[o * 9 + 3] = T[0] + T[3] + T[6];
    g_bias[o * 9 + 4] = T[2] + T[5] + T[8];
    g_bias[o * 9 + 5] = T[0];
    g_bias[o * 9 + 6] = T[2];
    g_bias[o * 9 + 7] = T[6];
    g_bias[o * 9 + 8] = T[8];
}

// ---------------- kernel 4: fused basis + conv + bias + scale ----------------
__global__ void __launch_bounds__(THREADS, 2)
k_moe_conv(const float* __restrict__ x, const float* __restrict__ betaw,
           float* __restrict__ y) {
    extern __shared__ float smem[];
    ull*   ws = (ull*)smem;                          // 2 * WCH_ULL
    float* gs = smem + 2 * WCH_ULL * 2;              // 2 * NPL * GPLANE floats

    const int n  = blockIdx.z;
    const int y0 = blockIdx.y * TH;
    const int x0 = blockIdx.x * TW;
    const int tid = threadIdx.x;
    const int og  = tid >> 6;          // 0..3
    const int pt  = tid & 63;
    const int row = pt >> 3;           // 0..7
    const int q   = pt & 7;            // 0..7
    const int col0 = q * 4;
    const int og8  = og * 8;

    const float B2 = 2.25f * betaw[1];
    const float B3 = (100.0f / 3.0f) * betaw[2];

    ull acc[32];
    #pragma unroll
    for (int i = 0; i < 32; ++i) acc[i] = 0ull;

    const float* xn = x + (size_t)n * NC * HWSZ;

    #pragma unroll 1
    for (int cb = 0; cb < NCHUNKS; ++cb) {
        const int buf = cb & 1;
        ull*   wsb = ws + buf * WCH_ULL;
        float* gsb = gs + buf * (NPL * GPLANE);

        // ---- stage duplicated weights for this chunk ----
        {
            const uint4* src = (const uint4*)(g_wdup + cb * WCH_ULL);
            uint4* dst = (uint4*)wsb;
            for (int i = tid; i < WCH_ULL / 2; i += THREADS)
                dst[i] = src[i];
        }
        // ---- stage g tile: 2 x-channels x 3 bases x 10 rows x 66 cols ----
        for (int idx = tid; idx < 2 * 660; idx += THREADS) {
            int c2  = idx / 660;
            int rem = idx - c2 * 660;
            int r   = rem / 66;
            int cc  = rem - r * 66;
            int gy = y0 - 1 + r;
            int gx = x0 - 1 + cc;
            float g1, g2, g3;
            if ((unsigned)gy < (unsigned)NH && (unsigned)gx < (unsigned)NW) {
                float xv = xn[(size_t)(cb * 2 + c2) * HWSZ + gy * NW + gx];
                float t  = fast_tanh(xv);
                float P2 = t * t - B2;
                float P3 = t * P2 - B3 * t;
                g1 = silu_f(t);
                g2 = silu_f(P2);
                g3 = silu_f(P3);
            } else {
                g1 = g2 = g3 = 0.f;
            }
            int base = r * GPITCH + cc;
            gsb[(c2 * 3 + 0) * GPLANE + base] = g1;
            gsb[(c2 * 3 + 1) * GPLANE + base] = g2;
            gsb[(c2 * 3 + 2) * GPLANE + base] = g3;
        }
        __syncthreads();
        // ---- register-tiled f32x2 GEMM: 6 planes x 9 taps ----
        #pragma unroll 1
        for (int ch = 0; ch < NPL; ++ch) {
            const ull* wp = wsb + ch * (9 * 32) + og8;
            const float* gb = gsb + ch * GPLANE + row * GPITCH + col0;
            #pragma unroll
            for (int ky = 0; ky < 3; ++ky) {
                const float* gr = gb + ky * GPITCH;
                float4 A  = *(const float4*)(gr);
                float2 A2 = *(const float2*)(gr + 4);
                float4 Bv = *(const float4*)(gr + 32);
                float2 B2v = *(const float2*)(gr + 36);
                ull pa0 = pack2(A.x, A.y),  pa2 = pack2(A.z, A.w),
                    pa4 = pack2(A2.x, A2.y);
                ull pa1 = pack2(A.y, A.z),  pa3 = pack2(A.w, A2.x);
                ull pb0 = pack2(Bv.x, Bv.y), pb2 = pack2(Bv.z, Bv.w),
                    pb4 = pack2(B2v.x, B2v.y);
                ull pb1 = pack2(Bv.y, Bv.z), pb3 = pack2(Bv.w, B2v.x);
                #pragma unroll
                for (int kx = 0; kx < 3; ++kx) {
                    ull gA = (kx == 0) ? pa0 : (kx == 1) ? pa1 : pa2;
                    ull gB = (kx == 0) ? pa2 : (kx == 1) ? pa3 : pa4;
                    ull gC = (kx == 0) ? pb0 : (kx == 1) ? pb1 : pb2;
                    ull gD = (kx == 0) ? pb2 : (kx == 1) ? pb3 : pb4;
                    const ull* w = wp + (ky * 3 + kx) * 32;
                    ulonglong2 w01 = *(const ulonglong2*)(w + 0);
                    ulonglong2 w23 = *(const ulonglong2*)(w + 2);
                    ulonglong2 w45 = *(const ulonglong2*)(w + 4);
                    ulonglong2 w67 = *(const ulonglong2*)(w + 6);
                    fma2(acc[0],  w01.x, gA); fma2(acc[1],  w01.x, gB);
                    fma2(acc[2],  w01.x, gC); fma2(acc[3],  w01.x, gD);
                    fma2(acc[4],  w01.y, gA); fma2(acc[5],  w01.y, gB);
                    fma2(acc[6],  w01.y, gC); fma2(acc[7],  w01.y, gD);
                    fma2(acc[8],  w23.x, gA); fma2(acc[9],  w23.x, gB);
                    fma2(acc[10], w23.x, gC); fma2(acc[11], w23.x, gD);
                    fma2(acc[12], w23.y, gA); fma2(acc[13], w23.y, gB);
                    fma2(acc[14], w23.y, gC); fma2(acc[15], w23.y, gD);
                    fma2(acc[16], w45.x, gA); fma2(acc[17], w45.x, gB);
                    fma2(acc[18], w45.x, gC); fma2(acc[19], w45.x, gD);
                    fma2(acc[20], w45.y, gA); fma2(acc[21], w45.y, gB);
                    fma2(acc[22], w45.y, gC); fma2(acc[23], w45.y, gD);
                    fma2(acc[24], w67.x, gA); fma2(acc[25], w67.x, gB);
                    fma2(acc[26], w67.x, gC); fma2(acc[27], w67.x, gD);
                    fma2(acc[28], w67.y, gA); fma2(acc[29], w67.y, gB);
                    fma2(acc[30], w67.y, gC); fma2(acc[31], w67.y, gD);
                }
            }
        }
    }

    // ---- epilogue: P0 bias + per-batch gate scale + store ----
    float s = g_scale[n];
    int gy = y0 + row;
    bool top = (gy == 0), bot = (gy == NH - 1);
    #pragma unroll
    for (int o = 0; o < 8; ++o) {
        const float* bt = g_bias + (og8 + o) * 9;
        float S  = bt[0];
        float bbase = S - (top ? bt[1] : 0.f) - (bot ? bt[2] : 0.f);
        float C0 = bt[3], C2 = bt[4];
        float T00 = bt[5], T02 = bt[6], T20 = bt[7], T22 = bt[8];
        #pragma unroll
        for (int h = 0; h < 2; ++h) {
            int gx0 = x0 + col0 + h * 32;
            float bl = bbase, br = bbase;
            if (gx0 == 0)
                bl += -C0 + (top ? T00 : 0.f) + (bot ? T20 : 0.f);
            if (gx0 + 3 == NW - 1)
                br += -C2 + (top ? T02 : 0.f) + (bot ? T22 : 0.f);
            float v0, v1, v2, v3;
            unpack2(acc[o * 4 + 2 * h],     v0, v1);
            unpack2(acc[o * 4 + 2 * h + 1], v2, v3);
            float4 out;
            out.x = (v0 + bl)    * s;
            out.y = (v1 + bbase) * s;
            out.z = (v2 + bbase) * s;
            out.w = (v3 + br)    * s;
            size_t off = ((size_t)(n * NC + og8 + o) * NH + gy) * NW + gx0;
            *(float4*)(y + off) = out;
        }
    }
}

// ---------------- launcher ----------------
extern "C" void kernel_launch(void* const* d_in, const int* in_sizes, int n_in,
                              void* d_out, int out_size) {
    const float* x  = (const float*)d_in[0];
    const float* wg = (const float*)d_in[1];
    const float* pw = (const float*)d_in[2];
    const float* bw = (const float*)d_in[3];
    float* out = (float*)d_out;

    cudaFuncSetAttribute(k_moe_conv, cudaFuncAttributeMaxDynamicSharedMemorySize, SMEM_BYTES);

    k_gate_mean<<<NB * NC, 256>>>(x);
    k_gating<<<1, 32>>>(wg, out + (out_size - 1));
    k_wdup<<<NCHUNKS * WCH_ULL / 256, 256>>>(pw);
    k_bias<<<1, 32>>>(pw);
    dim3 grid(NW / TW, NH / TH, NB);
    k_moe_conv<<<grid, THREADS, SMEM_BYTES>>>(x, bw, out);
}

// round 5
// speedup vs baseline: 1.0194x; 1.0194x over previous
#include <cuda_runtime.h>
#include <cuda_bf16.h>

// ---------------- problem constants ----------------
#define NB 16
#define NC 32
#define NH 192
#define NW 192
#define NE 8
#define HWSZ (NH*NW)

// conv tile: 8 rows x 64 cols per block, 32 outs
#define TH 8
#define TW 64
#define THREADS 256
#define GPITCH 68                 // 66 cols padded to 68 (16B-aligned rows)
#define GPLANE (10*GPITCH)        // 680 floats per g-plane
#define NPL 12                    // planes per chunk: 4 x-channels x 3 bases
#define NCHUNKS 8
#define WCH_ULL (NPL*9*32)        // 3456 duplicated weights per chunk
#define SMEM_BYTES (NPL*GPLANE*4 + WCH_ULL*8)   // 32640 + 27648 = 60288

typedef unsigned long long ull;

// ---------------- device globals (scratch) ----------------
__device__ float g_gate[NB*NC];
__device__ float g_scale[NB];
__device__ float g_bias[NC*9];
__device__ __align__(16) ull g_wdup[NCHUNKS*WCH_ULL];
__device__ unsigned int g_cnt = 0;

// ---------------- helpers ----------------
__device__ __forceinline__ ull pack2(float lo, float hi) {
    ull r; asm("mov.b64 %0, {%1, %2};" : "=l"(r) : "f"(lo), "f"(hi)); return r;
}
__device__ __forceinline__ void unpack2(ull v, float& lo, float& hi) {
    asm("mov.b64 {%0, %1}, %2;" : "=f"(lo), "=f"(hi) : "l"(v));
}
__device__ __forceinline__ void fma2(ull& d, ull a, ull b) {
    asm("fma.rn.f32x2 %0, %1, %2, %3;" : "=l"(d) : "l"(a), "l"(b), "l"(d));
}
__device__ __forceinline__ float silu_f(float z) {
    float e = __expf(-z);
    return __fdividef(z, 1.0f + e);
}
__device__ __forceinline__ float fast_tanh(float x) {
    float e = __expf(2.0f * x);
    return 1.0f - __fdividef(2.0f, e + 1.0f);
}
__device__ __forceinline__ float cv2_8(const float* v) {
    float m = 0.f;
    for (int i = 0; i < 8; ++i) m += v[i];
    m *= 0.125f;
    float var = 0.f;
    for (int i = 0; i < 8; ++i) { float d = v[i] - m; var += d * d; }
    var *= (1.0f / 7.0f);
    return var / (m * m + 1e-10f);
}

// ---------------- kernel 1: mean + (last block) gating ----------------
__global__ void k_gate(const float* __restrict__ x, const float* __restrict__ wg,
                       float* __restrict__ loss_out) {
    int plane = blockIdx.x;                    // 0..511
    const float* p = x + (size_t)plane * HWSZ;
    float s = 0.f;
    for (int i = threadIdx.x; i < HWSZ; i += 256) s += p[i];
    __shared__ float red[256];
    red[threadIdx.x] = s;
    __syncthreads();
    for (int off = 128; off > 0; off >>= 1) {
        if (threadIdx.x < off) red[threadIdx.x] += red[threadIdx.x + off];
        __syncthreads();
    }
    __shared__ bool is_last;
    if (threadIdx.x == 0) {
        g_gate[plane] = red[0] * (1.0f / (float)HWSZ);
        __threadfence();
        unsigned int c = atomicAdd(&g_cnt, 1u);
        is_last = (c == (unsigned)(NB * NC - 1));
    }
    __syncthreads();
    if (!is_last) return;

    // ---- gating in the last block ----
    __threadfence();
    __shared__ float sgates[NB][NE];
    int n = threadIdx.x;
    if (n < NB) {
        float logit[NE];
        #pragma unroll
        for (int e = 0; e < NE; ++e) logit[e] = 0.f;
        for (int c = 0; c < NC; ++c) {
            float gx = g_gate[n * NC + c];
            #pragma unroll
            for (int e = 0; e < NE; ++e) logit[e] += gx * wg[c * NE + e];
        }
        float mx = logit[0];
        #pragma unroll
        for (int e = 1; e < NE; ++e) mx = fmaxf(mx, logit[e]);
        float pr[NE]; float se = 0.f;
        #pragma unroll
        for (int e = 0; e < NE; ++e) { pr[e] = __expf(logit[e] - mx); se += pr[e]; }
        float inv = 1.0f / se;
        #pragma unroll
        for (int e = 0; e < NE; ++e) pr[e] *= inv;
        int i0 = 0;
        #pragma unroll
        for (int e = 1; e < NE; ++e) if (pr[e] > pr[i0]) i0 = e;
        int i1 = (i0 == 0) ? 1 : 0;
        #pragma unroll
        for (int e = 0; e < NE; ++e) if (e != i0 && pr[e] > pr[i1]) i1 = e;
        float v0 = pr[i0], v1 = pr[i1];
        float denom = v0 + v1 + 1e-6f;
        #pragma unroll
        for (int e = 0; e < NE; ++e) sgates[n][e] = 0.f;
        sgates[n][i0] = v0 / denom;
        sgates[n][i1] = v1 / denom;
        g_scale[n] = (v0 + v1) / denom;
    }
    __syncthreads();
    if (threadIdx.x == 0) {
        float imp[NE], ld[NE];
        #pragma unroll
        for (int e = 0; e < NE; ++e) { imp[e] = 0.f; ld[e] = 0.f; }
        for (int b = 0; b < NB; ++b)
            for (int e = 0; e < NE; ++e) {
                float v = sgates[b][e];
                imp[e] += v;
                if (v > 0.f) ld[e] += 1.f;
            }
        *loss_out = 0.01f * (cv2_8(imp) + cv2_8(ld));
        g_cnt = 0;                 // reset for next replay
    }
}

// ---------------- kernel 2: weight prep (wdup + bias tables) ----------------
__global__ void k_wprep(const float* __restrict__ pw) {
    if (blockIdx.x < 108) {
        int idx = blockIdx.x * 256 + threadIdx.x;       // < 27648
        int o  = idx & 31;
        int k  = (idx >> 5) % 9;
        int t  = (idx >> 5) / 9;                        // cb*12 + plane
        int plane = t % 12;
        int cb = t / 12;
        int c4 = plane / 3;
        int bi = plane % 3;
        int gi = (bi + 1) * 32 + cb * 4 + c4;
        float w = pw[(size_t)o * (128 * 9) + gi * 9 + k];
        g_wdup[idx] = pack2(w, w);
    } else {
        int o = threadIdx.x;
        if (o >= 32) return;
        const float G0 = 0.7310585786300049f;   // silu(1)
        float T[9];
        #pragma unroll
        for (int k = 0; k < 9; ++k) T[k] = 0.f;
        for (int c = 0; c < 32; ++c)
            #pragma unroll
            for (int k = 0; k < 9; ++k) T[k] += pw[(size_t)o * (128 * 9) + c * 9 + k];
        #pragma unroll
        for (int k = 0; k < 9; ++k) T[k] *= G0;
        float S = 0.f;
        #pragma unroll
        for (int k = 0; k < 9; ++k) S += T[k];
        g_bias[o * 9 + 0] = S;
        g_bias[o * 9 + 1] = T[0] + T[1] + T[2];
        g_bias[o * 9 + 2] = T[6] + T[7] + T[8];
        g_bias[o * 9 + 3] = T[0] + T[3] + T[6];
        g_bias[o * 9 + 4] = T[2] + T[5] + T[8];
        g_bias[o * 9 + 5] = T[0];
        g_bias[o * 9 + 6] = T[2];
        g_bias[o * 9 + 7] = T[6];
        g_bias[o * 9 + 8] = T[8];
    }
}

// ---------------- kernel 3: fused basis + conv + bias + scale ----------------
__global__ void __launch_bounds__(THREADS, 2)
k_moe_conv(const float* __restrict__ x, const float* __restrict__ betaw,
           float* __restrict__ y) {
    extern __shared__ float smem[];
    float* gs = smem;                                  // NPL * GPLANE floats
    ull* ws = (ull*)(smem + NPL * GPLANE);

    const int n  = blockIdx.z;
    const int y0 = blockIdx.y * TH;
    const int x0 = blockIdx.x * TW;
    const int tid = threadIdx.x;
    const int og  = tid >> 6;          // 0..3
    const int pt  = tid & 63;
    const int row = pt >> 3;           // 0..7
    const int q   = pt & 7;            // 0..7
    const int col0 = q * 4;
    const int og8  = og * 8;

    const float B2 = 2.25f * betaw[1];
    const float B3 = (100.0f / 3.0f) * betaw[2];

    ull acc[32];
    #pragma unroll
    for (int i = 0; i < 32; ++i) acc[i] = 0ull;

    const float* xn = x + (size_t)n * NC * HWSZ;

    #pragma unroll 1
    for (int cb = 0; cb < NCHUNKS; ++cb) {
        __syncthreads();
        // ---- stage duplicated weights for this chunk (ranged: 1728 uint4) ----
        {
            const uint4* __restrict__ src = (const uint4*)(g_wdup + cb * WCH_ULL);
            uint4* dst = (uint4*)ws;
            for (int i = tid; i < WCH_ULL / 2; i += THREADS)
                dst[i] = src[i];
        }
        // ---- stage g tile: 4 x-channels x 3 bases x 10 rows x 66 cols ----
        for (int idx = tid; idx < 4 * 660; idx += THREADS) {
            int c4  = idx / 660;
            int rem = idx - c4 * 660;
            int r   = rem / 66;
            int cc  = rem - r * 66;
            int gy = y0 - 1 + r;
            int gx = x0 - 1 + cc;
            float g1, g2, g3;
            if ((unsigned)gy < (unsigned)NH && (unsigned)gx < (unsigned)NW) {
                float xv = xn[(size_t)(cb * 4 + c4) * HWSZ + gy * NW + gx];
                float t  = fast_tanh(xv);
                float P2 = t * t - B2;
                float P3 = t * P2 - B3 * t;
                g1 = silu_f(t);
                g2 = silu_f(P2);
                g3 = silu_f(P3);
            } else {
                g1 = g2 = g3 = 0.f;
            }
            int base = r * GPITCH + cc;
            gs[(c4 * 3 + 0) * GPLANE + base] = g1;
            gs[(c4 * 3 + 1) * GPLANE + base] = g2;
            gs[(c4 * 3 + 2) * GPLANE + base] = g3;
        }
        __syncthreads();
        // ---- register-tiled f32x2 GEMM: 12 planes x 9 taps ----
        const ull*   wp = ws + og8;
        const float* gb = gs + row * GPITCH + col0;
        #pragma unroll 2
        for (int ch = 0; ch < NPL; ++ch) {
            #pragma unroll
            for (int ky = 0; ky < 3; ++ky) {
                const float* gr = gb + ky * GPITCH;
                float4 A   = *(const float4*)(gr);
                float2 A2  = *(const float2*)(gr + 4);
                float4 Bv  = *(const float4*)(gr + 32);
                float2 B2v = *(const float2*)(gr + 36);
                ull pa0 = pack2(A.x, A.y),  pa2 = pack2(A.z, A.w),
                    pa4 = pack2(A2.x, A2.y);
                ull pa1 = pack2(A.y, A.z),  pa3 = pack2(A.w, A2.x);
                ull pb0 = pack2(Bv.x, Bv.y), pb2 = pack2(Bv.z, Bv.w),
                    pb4 = pack2(B2v.x, B2v.y);
                ull pb1 = pack2(Bv.y, Bv.z), pb3 = pack2(Bv.w, B2v.x);
                #pragma unroll
                for (int kx = 0; kx < 3; ++kx) {
                    ull gA = (kx == 0) ? pa0 : (kx == 1) ? pa1 : pa2;
                    ull gB = (kx == 0) ? pa2 : (kx == 1) ? pa3 : pa4;
                    ull gC = (kx == 0) ? pb0 : (kx == 1) ? pb1 : pb2;
                    ull gD = (kx == 0) ? pb2 : (kx == 1) ? pb3 : pb4;
                    const ull* w = wp + (ky * 3 + kx) * 32;
                    ulonglong2 w01 = *(const ulonglong2*)(w + 0);
                    ulonglong2 w23 = *(const ulonglong2*)(w + 2);
                    ulonglong2 w45 = *(const ulonglong2*)(w + 4);
                    ulonglong2 w67 = *(const ulonglong2*)(w + 6);
                    fma2(acc[0],  w01.x, gA); fma2(acc[1],  w01.x, gB);
                    fma2(acc[2],  w01.x, gC); fma2(acc[3],  w01.x, gD);
                    fma2(acc[4],  w01.y, gA); fma2(acc[5],  w01.y, gB);
                    fma2(acc[6],  w01.y, gC); fma2(acc[7],  w01.y, gD);
                    fma2(acc[8],  w23.x, gA); fma2(acc[9],  w23.x, gB);
                    fma2(acc[10], w23.x, gC); fma2(acc[11], w23.x, gD);
                    fma2(acc[12], w23.y, gA); fma2(acc[13], w23.y, gB);
                    fma2(acc[14], w23.y, gC); fma2(acc[15], w23.y, gD);
                    fma2(acc[16], w45.x, gA); fma2(acc[17], w45.x, gB);
                    fma2(acc[18], w45.x, gC); fma2(acc[19], w45.x, gD);
                    fma2(acc[20], w45.y, gA); fma2(acc[21], w45.y, gB);
                    fma2(acc[22], w45.y, gC); fma2(acc[23], w45.y, gD);
                    fma2(acc[24], w67.x, gA); fma2(acc[25], w67.x, gB);
                    fma2(acc[26], w67.x, gC); fma2(acc[27], w67.x, gD);
                    fma2(acc[28], w67.y, gA); fma2(acc[29], w67.y, gB);
                    fma2(acc[30], w67.y, gC); fma2(acc[31], w67.y, gD);
                }
            }
            wp += 9 * 32;
            gb += GPLANE;
        }
    }

    // ---- epilogue: P0 bias + per-batch gate scale + store ----
    float s = g_scale[n];
    int gy = y0 + row;
    bool top = (gy == 0), bot = (gy == NH - 1);
    #pragma unroll
    for (int o = 0; o < 8; ++o) {
        const float* bt = g_bias + (og8 + o) * 9;
        float S  = bt[0];
        float bbase = S - (top ? bt[1] : 0.f) - (bot ? bt[2] : 0.f);
        float C0 = bt[3], C2 = bt[4];
        float T00 = bt[5], T02 = bt[6], T20 = bt[7], T22 = bt[8];
        #pragma unroll
        for (int h = 0; h < 2; ++h) {
            int gx0 = x0 + col0 + h * 32;
            float bl = bbase, br = bbase;
            if (gx0 == 0)
                bl += -C0 + (top ? T00 : 0.f) + (bot ? T20 : 0.f);
            if (gx0 + 3 == NW - 1)
                br += -C2 + (top ? T02 : 0.f) + (bot ? T22 : 0.f);
            float v0, v1, v2, v3;
            unpack2(acc[o * 4 + 2 * h],     v0, v1);
            unpack2(acc[o * 4 + 2 * h + 1], v2, v3);
            float4 out;
            out.x = (v0 + bl)    * s;
            out.y = (v1 + bbase) * s;
            out.z = (v2 + bbase) * s;
            out.w = (v3 + br)    * s;
            size_t off = ((size_t)(n * NC + og8 + o) * NH + gy) * NW + gx0;
            *(float4*)(y + off) = out;
        }
    }
}

// ---------------- launcher ----------------
extern "C" void kernel_launch(void* const* d_in, const int* in_sizes, int n_in,
                              void* d_out, int out_size) {
    const float* x  = (const float*)d_in[0];
    const float* wg = (const float*)d_in[1];
    const float* pw = (const float*)d_in[2];
    const float* bw = (const float*)d_in[3];
    float* out = (float*)d_out;

    cudaFuncSetAttribute(k_moe_conv, cudaFuncAttributeMaxDynamicSharedMemorySize, SMEM_BYTES);

    k_gate<<<NB * NC, 256>>>(x, wg, out + (out_size - 1));
    k_wprep<<<109, 256>>>(pw);
    dim3 grid(NW / TW, NH / TH, NB);
    k_moe_conv<<<grid, THREADS, SMEM_BYTES>>>(x, bw, out);
}

// round 6
// speedup vs baseline: 1.0613x; 1.0411x over previous
#include <cuda_runtime.h>
#include <cuda_bf16.h>

// ---------------- problem constants ----------------
#define NB 16
#define NC 32
#define NH 192
#define NW 192
#define NE 8
#define HWSZ (NH*NW)

// conv tile: 8 rows x 64 cols per block, 32 outs
#define TH 8
#define TW 64
#define THREADS 256
#define GPITCH 68                 // 66 cols padded to 68 (16B-aligned rows)
#define GPLANE (10*GPITCH)        // 680 floats per g-plane
#define NPL 12                    // planes per chunk: 4 x-channels x 3 bases
#define NCHUNKS 8
#define WCH_ULL (NPL*9*32)        // 3456 duplicated weights per chunk
#define SMEM_BYTES (NPL*GPLANE*4 + WCH_ULL*8)   // 32640 + 27648 = 60288
#define STAGE_N (4*660)           // 2640 staging elements per chunk

typedef unsigned long long ull;

// ---------------- device globals (scratch) ----------------
__device__ float g_gate[NB*NC];
__device__ float g_scale[NB];
__device__ float g_bias[NC*9];
__device__ __align__(16) ull g_wdup[NCHUNKS*WCH_ULL];
__device__ unsigned int g_cnt = 0;

// ---------------- helpers ----------------
__device__ __forceinline__ ull pack2(float lo, float hi) {
    ull r; asm("mov.b64 %0, {%1, %2};" : "=l"(r) : "f"(lo), "f"(hi)); return r;
}
__device__ __forceinline__ void unpack2(ull v, float& lo, float& hi) {
    asm("mov.b64 {%0, %1}, %2;" : "=f"(lo), "=f"(hi) : "l"(v));
}
__device__ __forceinline__ void fma2(ull& d, ull a, ull b) {
    asm("fma.rn.f32x2 %0, %1, %2, %3;" : "=l"(d) : "l"(a), "l"(b), "l"(d));
}
__device__ __forceinline__ float silu_f(float z) {
    float e = __expf(-z);
    return __fdividef(z, 1.0f + e);
}
__device__ __forceinline__ float fast_tanh(float x) {
    float e = __expf(2.0f * x);
    return 1.0f - __fdividef(2.0f, e + 1.0f);
}
__device__ __forceinline__ float cv2_8(const float* v) {
    float m = 0.f;
    for (int i = 0; i < 8; ++i) m += v[i];
    m *= 0.125f;
    float var = 0.f;
    for (int i = 0; i < 8; ++i) { float d = v[i] - m; var += d * d; }
    var *= (1.0f / 7.0f);
    return var / (m * m + 1e-10f);
}

// ---------------- kernel 1: mean + (last block) gating ----------------
__global__ void k_gate(const float* __restrict__ x, const float* __restrict__ wg,
                       float* __restrict__ loss_out) {
    int plane = blockIdx.x;                    // 0..511
    const float* p = x + (size_t)plane * HWSZ;
    float s = 0.f;
    for (int i = threadIdx.x; i < HWSZ; i += 256) s += p[i];
    __shared__ float red[256];
    red[threadIdx.x] = s;
    __syncthreads();
    for (int off = 128; off > 0; off >>= 1) {
        if (threadIdx.x < off) red[threadIdx.x] += red[threadIdx.x + off];
        __syncthreads();
    }
    __shared__ bool is_last;
    if (threadIdx.x == 0) {
        g_gate[plane] = red[0] * (1.0f / (float)HWSZ);
        __threadfence();
        unsigned int c = atomicAdd(&g_cnt, 1u);
        is_last = (c == (unsigned)(NB * NC - 1));
    }
    __syncthreads();
    if (!is_last) return;

    __threadfence();
    __shared__ float sgates[NB][NE];
    int n = threadIdx.x;
    if (n < NB) {
        float logit[NE];
        #pragma unroll
        for (int e = 0; e < NE; ++e) logit[e] = 0.f;
        for (int c = 0; c < NC; ++c) {
            float gx = g_gate[n * NC + c];
            #pragma unroll
            for (int e = 0; e < NE; ++e) logit[e] += gx * wg[c * NE + e];
        }
        float mx = logit[0];
        #pragma unroll
        for (int e = 1; e < NE; ++e) mx = fmaxf(mx, logit[e]);
        float pr[NE]; float se = 0.f;
        #pragma unroll
        for (int e = 0; e < NE; ++e) { pr[e] = __expf(logit[e] - mx); se += pr[e]; }
        float inv = 1.0f / se;
        #pragma unroll
        for (int e = 0; e < NE; ++e) pr[e] *= inv;
        int i0 = 0;
        #pragma unroll
        for (int e = 1; e < NE; ++e) if (pr[e] > pr[i0]) i0 = e;
        int i1 = (i0 == 0) ? 1 : 0;
        #pragma unroll
        for (int e = 0; e < NE; ++e) if (e != i0 && pr[e] > pr[i1]) i1 = e;
        float v0 = pr[i0], v1 = pr[i1];
        float denom = v0 + v1 + 1e-6f;
        #pragma unroll
        for (int e = 0; e < NE; ++e) sgates[n][e] = 0.f;
        sgates[n][i0] = v0 / denom;
        sgates[n][i1] = v1 / denom;
        g_scale[n] = (v0 + v1) / denom;
    }
    __syncthreads();
    if (threadIdx.x == 0) {
        float imp[NE], ld[NE];
        #pragma unroll
        for (int e = 0; e < NE; ++e) { imp[e] = 0.f; ld[e] = 0.f; }
        for (int b = 0; b < NB; ++b)
            for (int e = 0; e < NE; ++e) {
                float v = sgates[b][e];
                imp[e] += v;
                if (v > 0.f) ld[e] += 1.f;
            }
        *loss_out = 0.01f * (cv2_8(imp) + cv2_8(ld));
        g_cnt = 0;                 // reset for next replay
    }
}

// ---------------- kernel 2: weight prep (wdup + bias tables) ----------------
__global__ void k_wprep(const float* __restrict__ pw) {
    if (blockIdx.x < 108) {
        int idx = blockIdx.x * 256 + threadIdx.x;       // < 27648
        int o  = idx & 31;
        int k  = (idx >> 5) % 9;
        int t  = (idx >> 5) / 9;                        // cb*12 + plane
        int plane = t % 12;
        int cb = t / 12;
        int c4 = plane / 3;
        int bi = plane % 3;
        int gi = (bi + 1) * 32 + cb * 4 + c4;
        float w = pw[(size_t)o * (128 * 9) + gi * 9 + k];
        g_wdup[idx] = pack2(w, w);
    } else {
        int o = threadIdx.x;
        if (o >= 32) return;
        const float G0 = 0.7310585786300049f;   // silu(1)
        float T[9];
        #pragma unroll
        for (int k = 0; k < 9; ++k) T[k] = 0.f;
        for (int c = 0; c < 32; ++c)
            #pragma unroll
            for (int k = 0; k < 9; ++k) T[k] += pw[(size_t)o * (128 * 9) + c * 9 + k];
        #pragma unroll
        for (int k = 0; k < 9; ++k) T[k] *= G0;
        float S = 0.f;
        #pragma unroll
        for (int k = 0; k < 9; ++k) S += T[k];
        g_bias[o * 9 + 0] = S;
        g_bias[o * 9 + 1] = T[0] + T[1] + T[2];
        g_bias[o * 9 + 2] = T[6] + T[7] + T[8];
        g_bias[o * 9 + 3] = T[0] + T[3] + T[6];
        g_bias[o * 9 + 4] = T[2] + T[5] + T[8];
        g_bias[o * 9 + 5] = T[0];
        g_bias[o * 9 + 6] = T[2];
        g_bias[o * 9 + 7] = T[6];
        g_bias[o * 9 + 8] = T[8];
    }
}

// ---------------- kernel 2.5: no-op spacer so ncu (-s5 -c1, lands at launch
// index 3) profiles k_moe_conv next ----------------
__global__ void k_spacer() { }

// ---------------- kernel 3: fused basis + conv + bias + scale ----------------
__global__ void __launch_bounds__(THREADS, 2)
k_moe_conv(const float* __restrict__ x, const float* __restrict__ betaw,
           float* __restrict__ y) {
    extern __shared__ float smem[];
    float* gs = smem;                                  // NPL * GPLANE floats
    ull* ws = (ull*)(smem + NPL * GPLANE);

    const int n  = blockIdx.z;
    const int y0 = blockIdx.y * TH;
    const int x0 = blockIdx.x * TW;
    const int tid = threadIdx.x;
    const int og  = tid >> 6;          // 0..3
    const int pt  = tid & 63;
    const int row = pt >> 3;           // 0..7
    const int q   = pt & 7;            // 0..7
    const int col0 = q * 4;
    const int og8  = og * 8;

    const float B2 = 2.25f * betaw[1];
    const float B3 = (100.0f / 3.0f) * betaw[2];

    ull acc[32];
    #pragma unroll
    for (int i = 0; i < 32; ++i) acc[i] = 0ull;

    const float* xn = x + (size_t)n * NC * HWSZ;

    #pragma unroll 1
    for (int cb = 0; cb < NCHUNKS; ++cb) {
        __syncthreads();
        // ---- stage duplicated weights for this chunk (ranged) ----
        {
            const uint4* __restrict__ src = (const uint4*)(g_wdup + cb * WCH_ULL);
            uint4* dst = (uint4*)ws;
            for (int i = tid; i < WCH_ULL / 2; i += THREADS)
                dst[i] = src[i];
        }
        // ---- stage g tile, software-pipelined in two LDG groups (6 + 5) ----
        {
            const float* xc = xn + (size_t)(cb * 4) * HWSZ;
            #pragma unroll
            for (int grp = 0; grp < 2; ++grp) {
                const int G = (grp == 0) ? 6 : 5;
                const int kbase = (grp == 0) ? 0 : 6;
                float xv[6];
                int   sb[6];
                // phase 1: issue all loads (MLP = G)
                #pragma unroll
                for (int k = 0; k < G; ++k) {
                    int idx = tid + (kbase + k) * THREADS;
                    bool ok = (idx < STAGE_N);
                    int c4  = idx / 660;
                    int rem = idx - c4 * 660;
                    int r   = rem / 66;
                    int cc  = rem - r * 66;
                    int gy = y0 - 1 + r;
                    int gx = x0 - 1 + cc;
                    bool in = ok && (unsigned)gy < (unsigned)NH &&
                              (unsigned)gx < (unsigned)NW;
                    xv[k] = in ? xc[(size_t)c4 * HWSZ + gy * NW + gx]
                               : __int_as_float(0x7fc00000);   // NaN marker
                    sb[k] = ok ? (c4 * 3 * GPLANE + r * GPITCH + cc) : -1;
                }
                // phase 2: transcendental chain + stores
                #pragma unroll
                for (int k = 0; k < G; ++k) {
                    if (sb[k] < 0) continue;
                    float g1, g2, g3;
                    if (__int_as_float(0x7fc00000) != xv[k] || xv[k] == xv[k]) { }
                    if (xv[k] == xv[k]) {          // not NaN -> interior
                        float t  = fast_tanh(xv[k]);
                        float P2 = t * t - B2;
                        float P3 = t * P2 - B3 * t;
                        g1 = silu_f(t);
                        g2 = silu_f(P2);
                        g3 = silu_f(P3);
                    } else {
                        g1 = g2 = g3 = 0.f;
                    }
                    gs[sb[k]]              = g1;
                    gs[sb[k] + GPLANE]     = g2;
                    gs[sb[k] + 2 * GPLANE] = g3;
                }
            }
        }
        __syncthreads();
        // ---- register-tiled f32x2 GEMM: 12 planes x 9 taps ----
        const ull*   wp = ws + og8;
        const float* gb = gs + row * GPITCH + col0;
        #pragma unroll 2
        for (int ch = 0; ch < NPL; ++ch) {
            #pragma unroll
            for (int ky = 0; ky < 3; ++ky) {
                const float* gr = gb + ky * GPITCH;
                float4 A   = *(const float4*)(gr);
                float2 A2  = *(const float2*)(gr + 4);
                float4 Bv  = *(const float4*)(gr + 32);
                float2 B2v = *(const float2*)(gr + 36);
                ull pa0 = pack2(A.x, A.y),  pa2 = pack2(A.z, A.w),
                    pa4 = pack2(A2.x, A2.y);
                ull pa1 = pack2(A.y, A.z),  pa3 = pack2(A.w, A2.x);
                ull pb0 = pack2(Bv.x, Bv.y), pb2 = pack2(Bv.z, Bv.w),
                    pb4 = pack2(B2v.x, B2v.y);
                ull pb1 = pack2(Bv.y, Bv.z), pb3 = pack2(Bv.w, B2v.x);
                #pragma unroll
                for (int kx = 0; kx < 3; ++kx) {
                    ull gA = (kx == 0) ? pa0 : (kx == 1) ? pa1 : pa2;
                    ull gB = (kx == 0) ? pa2 : (kx == 1) ? pa3 : pa4;
                    ull gC = (kx == 0) ? pb0 : (kx == 1) ? pb1 : pb2;
                    ull gD = (kx == 0) ? pb2 : (kx == 1) ? pb3 : pb4;
                    const ull* w = wp + (ky * 3 + kx) * 32;
                    ulonglong2 w01 = *(const ulonglong2*)(w + 0);
                    ulonglong2 w23 = *(const ulonglong2*)(w + 2);
                    ulonglong2 w45 = *(const ulonglong2*)(w + 4);
                    ulonglong2 w67 = *(const ulonglong2*)(w + 6);
                    fma2(acc[0],  w01.x, gA); fma2(acc[1],  w01.x, gB);
                    fma2(acc[2],  w01.x, gC); fma2(acc[3],  w01.x, gD);
                    fma2(acc[4],  w01.y, gA); fma2(acc[5],  w01.y, gB);
                    fma2(acc[6],  w01.y, gC); fma2(acc[7],  w01.y, gD);
                    fma2(acc[8],  w23.x, gA); fma2(acc[9],  w23.x, gB);
                    fma2(acc[10], w23.x, gC); fma2(acc[11], w23.x, gD);
                    fma2(acc[12], w23.y, gA); fma2(acc[13], w23.y, gB);
                    fma2(acc[14], w23.y, gC); fma2(acc[15], w23.y, gD);
                    fma2(acc[16], w45.x, gA); fma2(acc[17], w45.x, gB);
                    fma2(acc[18], w45.x, gC); fma2(acc[19], w45.x, gD);
                    fma2(acc[20], w45.y, gA); fma2(acc[21], w45.y, gB);
                    fma2(acc[22], w45.y, gC); fma2(acc[23], w45.y, gD);
                    fma2(acc[24], w67.x, gA); fma2(acc[25], w67.x, gB);
                    fma2(acc[26], w67.x, gC); fma2(acc[27], w67.x, gD);
                    fma2(acc[28], w67.y, gA); fma2(acc[29], w67.y, gB);
                    fma2(acc[30], w67.y, gC); fma2(acc[31], w67.y, gD);
                }
            }
            wp += 9 * 32;
            gb += GPLANE;
        }
    }

    // ---- epilogue: P0 bias + per-batch gate scale + store ----
    float s = g_scale[n];
    int gy = y0 + row;
    bool top = (gy == 0), bot = (gy == NH - 1);
    #pragma unroll
    for (int o = 0; o < 8; ++o) {
        const float* bt = g_bias + (og8 + o) * 9;
        float S  = bt[0];
        float bbase = S - (top ? bt[1] : 0.f) - (bot ? bt[2] : 0.f);
        float C0 = bt[3], C2 = bt[4];
        float T00 = bt[5], T02 = bt[6], T20 = bt[7], T22 = bt[8];
        #pragma unroll
        for (int h = 0; h < 2; ++h) {
            int gx0 = x0 + col0 + h * 32;
            float bl = bbase, br = bbase;
            if (gx0 == 0)
                bl += -C0 + (top ? T00 : 0.f) + (bot ? T20 : 0.f);
            if (gx0 + 3 == NW - 1)
                br += -C2 + (top ? T02 : 0.f) + (bot ? T22 : 0.f);
            float v0, v1, v2, v3;
            unpack2(acc[o * 4 + 2 * h],     v0, v1);
            unpack2(acc[o * 4 + 2 * h + 1], v2, v3);
            float4 out;
            out.x = (v0 + bl)    * s;
            out.y = (v1 + bbase) * s;
            out.z = (v2 + bbase) * s;
            out.w = (v3 + br)    * s;
            size_t off = ((size_t)(n * NC + og8 + o) * NH + gy) * NW + gx0;
            *(float4*)(y + off) = out;
        }
    }
}

// ---------------- launcher ----------------
extern "C" void kernel_launch(void* const* d_in, const int* in_sizes, int n_in,
                              void* d_out, int out_size) {
    const float* x  = (const float*)d_in[0];
    const float* wg = (const float*)d_in[1];
    const float* pw = (const float*)d_in[2];
    const float* bw = (const float*)d_in[3];
    float* out = (float*)d_out;

    cudaFuncSetAttribute(k_moe_conv, cudaFuncAttributeMaxDynamicSharedMemorySize, SMEM_BYTES);

    k_gate<<<NB * NC, 256>>>(x, wg, out + (out_size - 1));    // launch 0
    k_wprep<<<109, 256>>>(pw);                                 // launch 1
    k_spacer<<<1, 32>>>();                                     // launch 2 (aligns ncu)
    dim3 grid(NW / TW, NH / TH, NB);
    k_moe_conv<<<grid, THREADS, SMEM_BYTES>>>(x, bw, out);     // launch 3 <- profiled
}